// round 1
// baseline (speedup 1.0000x reference)
#include <cuda_runtime.h>

// NonLocalMeansSmoothing: x [8,256,256,8] fp32 -> same shape.
// K=5, sigma=1, h=1. reflect padding.
//
// Key simplification: reference computes w = exp(-diff) * gk, then normalizes
// over the 25 taps. gk's global normalization (divide by sum) cancels in the
// renormalization, so w ∝ exp(-(diff + 0.5*(di^2+dj^2))). One expf per tap.

#define BATCH 8
#define NX 256
#define NY 256
#define NCH 8
#define TILE 32
#define HALO 2
#define SMW (TILE + 2 * HALO)   // 36

__device__ __forceinline__ int refl(int p, int n) {
    if (p < 0) p = -p;
    if (p >= n) p = 2 * n - 2 - p;
    return p;
}

__global__ __launch_bounds__(1024, 1)
void nlm_kernel(const float* __restrict__ x, float* __restrict__ out) {
    // Two float4 planes (channels 0-3 and 4-7). Lane-adjacent pixels are
    // 16 B apart in smem -> conflict-free LDS.128 within quarter-warps.
    __shared__ float4 sm0[SMW][SMW];
    __shared__ float4 sm1[SMW][SMW];

    const int b   = blockIdx.z;
    const int ti0 = blockIdx.y * TILE;   // row (nx) tile origin
    const int tj0 = blockIdx.x * TILE;   // col (ny) tile origin
    const int tid = threadIdx.y * 32 + threadIdx.x;

    const float* xb = x + (size_t)b * NX * NY * NCH;

    // Cooperative halo load: 36*36 = 1296 pixels, 1024 threads.
    for (int p = tid; p < SMW * SMW; p += 1024) {
        int r = p / SMW;
        int c = p - r * SMW;
        int gi = refl(ti0 + r - HALO, NX);
        int gj = refl(tj0 + c - HALO, NY);
        const float4* src = reinterpret_cast<const float4*>(
            xb + ((size_t)gi * NY + gj) * NCH);
        sm0[r][c] = src[0];
        sm1[r][c] = src[1];
    }
    __syncthreads();

    const int li = threadIdx.y + HALO;
    const int lj = threadIdx.x + HALO;

    const float4 c0 = sm0[li][lj];
    const float4 c1 = sm1[li][lj];

    float4 a0 = make_float4(0.f, 0.f, 0.f, 0.f);
    float4 a1 = make_float4(0.f, 0.f, 0.f, 0.f);
    float wsum = 0.f;

#pragma unroll
    for (int di = -HALO; di <= HALO; di++) {
#pragma unroll
        for (int dj = -HALO; dj <= HALO; dj++) {
            const float4 n0 = sm0[li + di][lj + dj];
            const float4 n1 = sm1[li + di][lj + dj];
            float d;
            float t;
            t = c0.x - n0.x; d  = t * t;
            t = c0.y - n0.y; d += t * t;
            t = c0.z - n0.z; d += t * t;
            t = c0.w - n0.w; d += t * t;
            t = c1.x - n1.x; d += t * t;
            t = c1.y - n1.y; d += t * t;
            t = c1.z - n1.z; d += t * t;
            t = c1.w - n1.w; d += t * t;
            const float g = 0.5f * (float)(di * di + dj * dj);
            const float w = __expf(-(d + g));
            wsum += w;
            a0.x += w * n0.x;  a0.y += w * n0.y;
            a0.z += w * n0.z;  a0.w += w * n0.w;
            a1.x += w * n1.x;  a1.y += w * n1.y;
            a1.z += w * n1.z;  a1.w += w * n1.w;
        }
    }

    const float inv = __fdividef(1.f, wsum);
    a0.x *= inv; a0.y *= inv; a0.z *= inv; a0.w *= inv;
    a1.x *= inv; a1.y *= inv; a1.z *= inv; a1.w *= inv;

    const int gi = ti0 + threadIdx.y;
    const int gj = tj0 + threadIdx.x;
    float4* dst = reinterpret_cast<float4*>(
        out + (((size_t)b * NX + gi) * NY + gj) * NCH);
    dst[0] = a0;
    dst[1] = a1;
}

extern "C" void kernel_launch(void* const* d_in, const int* in_sizes, int n_in,
                              void* d_out, int out_size) {
    const float* x = (const float*)d_in[0];
    float* out = (float*)d_out;
    dim3 block(32, 32, 1);
    dim3 grid(NY / TILE, NX / TILE, BATCH);  // (8, 8, 8)
    nlm_kernel<<<grid, block>>>(x, out);
}